// round 3
// baseline (speedup 1.0000x reference)
#include <cuda_runtime.h>

// YOLO loss reduction — streaming version.
//
// Empirical finding (R2 ncu): DRAM moves the FULL 774MB regardless of which
// sectors are requested (cell stride 120B < 128B line => every line needed).
// So minimum traffic is a full read of both tensors; the only lever left is
// DRAM efficiency. This kernel issues a perfectly sequential, fully
// coalesced float4 stream over all bytes, decoding the needed channels
// (0..4 of 30) on the fly into compact SMEM, then computes per-cell loss.
//
// Tile = 512 cells = 3840 float4 per tensor (exact, 15 f4/thread @ 256 thr).
// SMEM compact layout: 7 floats per cell (stride 7 => conflict-free reads).
// Deterministic reduction: per-block double partial, last-arriving block
// (wraparound atomicInc, self-resetting => CUDA-graph safe) folds partials.

#define TPB 256
#define CELLS_PER_TILE 512
#define F4_PER_TILE (CELLS_PER_TILE * 30 / 4)   // 3840
#define K_STEPS (F4_PER_TILE / TPB)             // 15
#define MAX_BLOCKS 8192

__device__ double g_partials[MAX_BLOCKS];
__device__ unsigned int g_counter = 0;          // wraps to 0 every launch

__global__ __launch_bounds__(TPB)
void yolo_loss_kernel(const float4* __restrict__ pre4,
                      const float4* __restrict__ gt4,
                      float* __restrict__ out,
                      int ncells, long long total_f4) {
    __shared__ float sp[CELLS_PER_TILE * 7];    // 14336 B
    __shared__ float sg[CELLS_PER_TILE * 7];    // 14336 B
    __shared__ double swarp[TPB / 32];
    __shared__ bool is_last;

    const int tid = threadIdx.x;
    const int cell0 = blockIdx.x * CELLS_PER_TILE;
    const long long base_f4 = (long long)cell0 * 30 / 4;  // tile start (f4)
    const int cit = min(CELLS_PER_TILE, ncells - cell0);   // cells in tile

    // ---- coalesced streaming load of the whole tile + on-the-fly decode.
    // Local f4 index i = tid + k*256 in [0,3840). With s = i mod 15, the
    // four floats of this f4 sit at positions f = 4s+c within a 60-float
    // (2-cell) group; needed iff f in [0,5) (cell 2q, ch f) or
    // [30,35) (cell 2q+1, ch f-30), q = i/15.
    #pragma unroll
    for (int k = 0; k < K_STEPS; ++k) {
        const int i = tid + k * TPB;
        const int q = i / 15;
        const int s = i - q * 15;
        const int f0 = 4 * s;                    // 0,4,8,...,56

        float4 vp = make_float4(0.f, 0.f, 0.f, 0.f);
        float4 vg = make_float4(0.f, 0.f, 0.f, 0.f);
        if (base_f4 + i < total_f4) {
            vp = __ldg(pre4 + base_f4 + i);
            vg = __ldg(gt4  + base_f4 + i);
        }

        const float pc[4] = {vp.x, vp.y, vp.z, vp.w};
        const float gc[4] = {vg.x, vg.y, vg.z, vg.w};
        #pragma unroll
        for (int c = 0; c < 4; ++c) {
            const int f = f0 + c;
            if (f < 5) {
                const int cl = 2 * q;
                if (cl < cit) { sp[cl * 7 + f] = pc[c]; sg[cl * 7 + f] = gc[c]; }
            } else if (f >= 30 && f < 35) {
                const int cl = 2 * q + 1;
                if (cl < cit) { sp[cl * 7 + (f - 30)] = pc[c]; sg[cl * 7 + (f - 30)] = gc[c]; }
            }
        }
    }
    __syncthreads();

    // ---- compute: 2 cells per thread from compact SMEM (stride 7, no conflicts)
    double acc = 0.0;
    #pragma unroll
    for (int half = 0; half < 2; ++half) {
        const int cl = tid + half * TPB;
        if (cl < cit) {
            const int b = cl * 7;
            float d0 = sp[b + 0] - sg[b + 0];
            float d1 = sp[b + 1] - sg[b + 1];
            float d2 = sp[b + 2] - sg[b + 2];
            float d3 = sp[b + 3] - sg[b + 3];
            float g4v = sg[b + 4];
            float dc = sp[b + 4] - g4v;
            float coord = fmaf(d0, d0, fmaf(d1, d1, fmaf(d2, d2, d3 * d3)));
            float conf = dc * dc;
            float cell_loss = (g4v == 1.0f) ? fmaf(5.0f, coord, 10.0f * conf)
                                            : 0.5f * conf;
            acc += (double)cell_loss;
        }
    }

    // ---- block reduction (double) -> one partial per block
    const unsigned full = 0xffffffffu;
    #pragma unroll
    for (int s = 16; s > 0; s >>= 1) acc += __shfl_down_sync(full, acc, s);
    if ((tid & 31) == 0) swarp[tid >> 5] = acc;
    __syncthreads();
    if (tid < 32) {
        double v = (tid < (TPB / 32)) ? swarp[tid] : 0.0;
        #pragma unroll
        for (int s = 16; s > 0; s >>= 1) v += __shfl_down_sync(full, v, s);
        if (tid == 0) g_partials[blockIdx.x] = v;
    }

    // ---- last-arriving block folds partials (deterministic order)
    if (tid == 0) {
        __threadfence();
        unsigned old = atomicInc(&g_counter, gridDim.x - 1);
        is_last = (old == gridDim.x - 1);
    }
    __syncthreads();
    if (is_last) {
        __threadfence();
        double v = 0.0;
        for (int i = tid; i < (int)gridDim.x; i += TPB) v += g_partials[i];
        #pragma unroll
        for (int s = 16; s > 0; s >>= 1) v += __shfl_down_sync(full, v, s);
        if ((tid & 31) == 0) swarp[tid >> 5] = v;
        __syncthreads();
        if (tid < 32) {
            double w = (tid < (TPB / 32)) ? swarp[tid] : 0.0;
            #pragma unroll
            for (int s = 16; s > 0; s >>= 1) w += __shfl_down_sync(full, w, s);
            if (tid == 0) out[0] = (float)w;
        }
    }
}

extern "C" void kernel_launch(void* const* d_in, const int* in_sizes, int n_in,
                              void* d_out, int out_size) {
    const float4* pre4 = (const float4*)d_in[0];
    const float4* gt4  = (const float4*)d_in[1];
    float* out = (float*)d_out;

    const int nelem  = in_sizes[0];
    const int ncells = nelem / 30;
    const long long total_f4 = (long long)nelem / 4;
    int ntiles = (ncells + CELLS_PER_TILE - 1) / CELLS_PER_TILE;  // 6272
    if (ntiles > MAX_BLOCKS) ntiles = MAX_BLOCKS;                 // (not hit)

    yolo_loss_kernel<<<ntiles, TPB>>>(pre4, gt4, out, ncells, total_f4);
}

// round 4
// speedup vs baseline: 1.0888x; 1.0888x over previous
#include <cuda_runtime.h>

// YOLO loss reduction — sequential stream, zero-SMEM, per-float decomposition.
//
// Both tensors must be fully fetched from DRAM (every 128B line holds needed
// bytes: cell period 120B). This kernel issues a perfectly sequential,
// fully-coalesced float4 request stream over all bytes and computes loss
// contributions in-register. Per 60-float (2-cell) group, only f4 slots
// s in {0,1,7,8} carry needed channels; mask (gt ch4) is fetched with one
// extra scalar load for s in {0,7} (L1/L2 hit, adjacent line).
//
//   loss = sum_cells [ g4==1 ? 5*sum(d_c^2,c=0..3) + 10*d4^2 : 0.5*d4^2 ]
//
// Deterministic reduction: float acc per thread (<=15 terms), double block
// reduce, last-arriving block (wraparound atomicInc, self-resetting) folds.

#define TPB 256
#define CELLS_PER_TILE 512
#define F4_PER_TILE (CELLS_PER_TILE * 30 / 4)   // 3840
#define K_STEPS (F4_PER_TILE / TPB)             // 15
#define MAX_BLOCKS 8192

__device__ double g_partials[MAX_BLOCKS];
__device__ unsigned int g_counter = 0;          // wraps to 0 every launch

__global__ __launch_bounds__(TPB)
void yolo_loss_kernel(const float4* __restrict__ pre4,
                      const float4* __restrict__ gt4,
                      const float* __restrict__ gt_f,
                      float* __restrict__ out,
                      long long total_f4) {
    __shared__ double swarp[TPB / 32];
    __shared__ bool is_last;

    const int tid = threadIdx.x;
    const long long base_f4 = (long long)blockIdx.x * F4_PER_TILE;

    // s_k = (tid + k*256) mod 15 ; 256 mod 15 == 1 -> s advances by 1 per step.
    int s = tid % 15;

    float acc = 0.0f;

    #pragma unroll
    for (int k = 0; k < K_STEPS; ++k) {
        const long long idx = base_f4 + tid + k * TPB;
        if (idx < total_f4) {
            const float4 vp = __ldg(pre4 + idx);
            const float4 vg = __ldg(gt4 + idx);

            if (s == 0) {
                // even cell: coords ch0..3; mask at float +4 (same line)
                const float g4 = __ldg(gt_f + 4 * idx + 4);
                if (g4 == 1.0f) {
                    float d0 = vp.x - vg.x, d1 = vp.y - vg.y;
                    float d2 = vp.z - vg.z, d3 = vp.w - vg.w;
                    acc += 5.0f * fmaf(d0, d0, fmaf(d1, d1, fmaf(d2, d2, d3 * d3)));
                }
            } else if (s == 1) {
                // even cell: conf ch4 = .x, mask = vg.x
                const float d = vp.x - vg.x;
                acc += ((vg.x == 1.0f) ? 10.0f : 0.5f) * d * d;
            } else if (s == 7) {
                // odd cell: coords ch0,1 = .z,.w; mask at float +6
                const float g4 = __ldg(gt_f + 4 * idx + 6);
                if (g4 == 1.0f) {
                    float d2 = vp.z - vg.z, d3 = vp.w - vg.w;
                    acc += 5.0f * fmaf(d2, d2, d3 * d3);
                }
            } else if (s == 8) {
                // odd cell: coords ch2,3 = .x,.y; conf ch4 = .z, mask = vg.z
                float d0 = vp.x - vg.x, d1 = vp.y - vg.y;
                float dc = vp.z - vg.z;
                if (vg.z == 1.0f) {
                    acc += fmaf(5.0f, fmaf(d0, d0, d1 * d1), 10.0f * dc * dc);
                } else {
                    acc += 0.5f * dc * dc;
                }
            }
        }
        // advance s by one, wrap at 15
        s = (s == 14) ? 0 : s + 1;
    }

    // ---- block reduction (double) -> one partial per block
    double dacc = (double)acc;
    const unsigned full = 0xffffffffu;
    #pragma unroll
    for (int sh = 16; sh > 0; sh >>= 1) dacc += __shfl_down_sync(full, dacc, sh);
    if ((tid & 31) == 0) swarp[tid >> 5] = dacc;
    __syncthreads();
    if (tid < 32) {
        double v = (tid < (TPB / 32)) ? swarp[tid] : 0.0;
        #pragma unroll
        for (int sh = 16; sh > 0; sh >>= 1) v += __shfl_down_sync(full, v, sh);
        if (tid == 0) g_partials[blockIdx.x] = v;
    }

    // ---- last-arriving block folds partials (deterministic order)
    if (tid == 0) {
        __threadfence();
        unsigned old = atomicInc(&g_counter, gridDim.x - 1);
        is_last = (old == gridDim.x - 1);
    }
    __syncthreads();
    if (is_last) {
        __threadfence();
        double v = 0.0;
        for (int i = tid; i < (int)gridDim.x; i += TPB) v += g_partials[i];
        #pragma unroll
        for (int sh = 16; sh > 0; sh >>= 1) v += __shfl_down_sync(full, v, sh);
        if ((tid & 31) == 0) swarp[tid >> 5] = v;
        __syncthreads();
        if (tid < 32) {
            double w = (tid < (TPB / 32)) ? swarp[tid] : 0.0;
            #pragma unroll
            for (int sh = 16; sh > 0; sh >>= 1) w += __shfl_down_sync(full, w, sh);
            if (tid == 0) out[0] = (float)w;
        }
    }
}

extern "C" void kernel_launch(void* const* d_in, const int* in_sizes, int n_in,
                              void* d_out, int out_size) {
    const float* pre = (const float*)d_in[0];
    const float* gt  = (const float*)d_in[1];
    float* out = (float*)d_out;

    const int nelem = in_sizes[0];
    const long long total_f4 = (long long)nelem / 4;
    int ntiles = (int)((total_f4 + F4_PER_TILE - 1) / F4_PER_TILE);  // 6272
    if (ntiles > MAX_BLOCKS) ntiles = MAX_BLOCKS;                    // not hit

    yolo_loss_kernel<<<ntiles, TPB>>>((const float4*)pre, (const float4*)gt,
                                      gt, out, total_f4);
}

// round 5
// speedup vs baseline: 1.2985x; 1.1926x over previous
#include <cuda_runtime.h>
#include <cstdint>

// YOLO loss reduction — TMA (cp.async.bulk) streaming pipeline.
//
// R2-R4 evidence: full 771MB must move from DRAM (128B-line fetch granularity,
// cell period 120B). SM-issued full-stream loads (R3/R4) go issue-bound before
// saturating DRAM. TMA bulk copies move the stream with ~zero SM instructions
// per byte: 3-stage SMEM ring, 256-cell tiles (30720B/tensor), one elected
// thread issues expect_tx + 2 bulk copies per stage; 256 consumer threads
// compute 1 cell each from SMEM (stride-30 LDS, 2-way conflicts only).
//
// Deterministic reduction: per-thread double acc -> block double reduce ->
// per-block partial -> last-arriving block (wraparound atomicInc,
// self-resetting => CUDA-graph replay safe) folds in fixed order.

#define TPB 256
#define TILE_CELLS 256
#define TILE_BYTES (TILE_CELLS * 30 * 4)       // 30720 per tensor
#define STAGES 3
#define SMEM_DYN (STAGES * 2 * TILE_BYTES)     // 184320 B
#define MAX_BLOCKS 1024

__device__ double g_partials[MAX_BLOCKS];
__device__ unsigned int g_counter = 0;         // wraps to 0 every launch

static __device__ __forceinline__ uint32_t smem_u32(const void* p) {
    return (uint32_t)__cvta_generic_to_shared(p);
}

static __device__ __forceinline__ void mbar_init(uint32_t mbar, uint32_t count) {
    asm volatile("mbarrier.init.shared.b64 [%0], %1;" :: "r"(mbar), "r"(count) : "memory");
}

static __device__ __forceinline__ void mbar_expect_tx(uint32_t mbar, uint32_t bytes) {
    asm volatile("mbarrier.arrive.expect_tx.shared.b64 _, [%0], %1;"
                 :: "r"(mbar), "r"(bytes) : "memory");
}

static __device__ __forceinline__ void mbar_wait(uint32_t mbar, uint32_t parity) {
    uint32_t done;
    asm volatile(
        "{\n\t.reg .pred p;\n\t"
        "mbarrier.try_wait.parity.acquire.cta.shared::cta.b64 p, [%1], %2;\n\t"
        "selp.b32 %0, 1, 0, p;\n\t}"
        : "=r"(done) : "r"(mbar), "r"(parity) : "memory");
    if (!done) {
        asm volatile(
            "{\n\t.reg .pred P1;\n\t"
            "WAIT_LOOP_%=:\n\t"
            "mbarrier.try_wait.parity.acquire.cta.shared::cta.b64 P1, [%0], %1, 0x989680;\n\t"
            "@P1 bra.uni WAIT_DONE_%=;\n\t"
            "bra.uni WAIT_LOOP_%=;\n\t"
            "WAIT_DONE_%=:\n\t}"
            :: "r"(mbar), "r"(parity) : "memory");
    }
}

static __device__ __forceinline__ void bulk_g2s(uint32_t dst_smem, const void* src_gmem,
                                                uint32_t bytes, uint32_t mbar) {
    asm volatile(
        "cp.async.bulk.shared::cluster.global.mbarrier::complete_tx::bytes "
        "[%0], [%1], %2, [%3];"
        :: "r"(dst_smem), "l"(src_gmem), "r"(bytes), "r"(mbar) : "memory");
}

__global__ __launch_bounds__(TPB)
void yolo_loss_tma(const float* __restrict__ pre,
                   const float* __restrict__ gt,
                   float* __restrict__ out,
                   int ncells, int ntiles, int tiles_per_blk) {
    extern __shared__ char dyn[];
    __shared__ uint64_t mbar_store[STAGES];
    __shared__ double swarp[TPB / 32];
    __shared__ bool is_last;

    const int tid = threadIdx.x;
    const uint32_t mbar0 = smem_u32(&mbar_store[0]);

    if (tid == 0) {
        #pragma unroll
        for (int s = 0; s < STAGES; ++s) mbar_init(mbar0 + 8u * s, 1);
    }
    __syncthreads();

    double acc = 0.0;

    // ---- scalar tail (non-full tiles); zero iterations for this shape
    if (blockIdx.x == 0) {
        for (int cell = ntiles * TILE_CELLS + tid; cell < ncells; cell += TPB) {
            const long long b = (long long)cell * 30;
            float d0 = __ldg(pre + b + 0) - __ldg(gt + b + 0);
            float d1 = __ldg(pre + b + 1) - __ldg(gt + b + 1);
            float d2 = __ldg(pre + b + 2) - __ldg(gt + b + 2);
            float d3 = __ldg(pre + b + 3) - __ldg(gt + b + 3);
            float g4 = __ldg(gt + b + 4);
            float dc = __ldg(pre + b + 4) - g4;
            float coord = fmaf(d0, d0, fmaf(d1, d1, fmaf(d2, d2, d3 * d3)));
            float conf = dc * dc;
            acc += (double)((g4 == 1.0f) ? fmaf(5.0f, coord, 10.0f * conf)
                                         : 0.5f * conf);
        }
    }

    // ---- this block's contiguous tile range
    const int t0 = blockIdx.x * tiles_per_blk;
    const int tend = min(t0 + tiles_per_blk, ntiles);
    const int nt = tend - t0;

    // ---- prologue: fill the ring
    if (tid == 0) {
        const int pfill = nt < STAGES ? nt : STAGES;
        for (int s = 0; s < pfill; ++s) {
            const uint32_t mb = mbar0 + 8u * s;
            const uint32_t dst = smem_u32(dyn) + (uint32_t)s * 2u * TILE_BYTES;
            const long long goff = (long long)(t0 + s) * TILE_CELLS * 30;
            mbar_expect_tx(mb, 2u * TILE_BYTES);
            bulk_g2s(dst, pre + goff, TILE_BYTES, mb);
            bulk_g2s(dst + TILE_BYTES, gt + goff, TILE_BYTES, mb);
        }
    }

    // ---- steady state
    for (int t = 0; t < nt; ++t) {
        const int s = t % STAGES;
        const uint32_t parity = (uint32_t)((t / STAGES) & 1);
        mbar_wait(mbar0 + 8u * s, parity);

        const float* sp = (const float*)(dyn + (size_t)s * 2 * TILE_BYTES);
        const float* sg = sp + TILE_CELLS * 30;
        const int b = tid * 30;
        float d0 = sp[b + 0] - sg[b + 0];
        float d1 = sp[b + 1] - sg[b + 1];
        float d2 = sp[b + 2] - sg[b + 2];
        float d3 = sp[b + 3] - sg[b + 3];
        float g4 = sg[b + 4];
        float dc = sp[b + 4] - g4;
        float coord = fmaf(d0, d0, fmaf(d1, d1, fmaf(d2, d2, d3 * d3)));
        float conf = dc * dc;
        acc += (double)((g4 == 1.0f) ? fmaf(5.0f, coord, 10.0f * conf)
                                     : 0.5f * conf);

        __syncthreads();   // all lanes done reading stage s

        if (tid == 0 && t + STAGES < nt) {
            const uint32_t mb = mbar0 + 8u * s;
            const uint32_t dst = smem_u32(dyn) + (uint32_t)s * 2u * TILE_BYTES;
            const long long goff = (long long)(t0 + t + STAGES) * TILE_CELLS * 30;
            mbar_expect_tx(mb, 2u * TILE_BYTES);
            bulk_g2s(dst, pre + goff, TILE_BYTES, mb);
            bulk_g2s(dst + TILE_BYTES, gt + goff, TILE_BYTES, mb);
        }
    }

    // ---- block reduction (double) -> one partial per block
    const unsigned full = 0xffffffffu;
    #pragma unroll
    for (int sh = 16; sh > 0; sh >>= 1) acc += __shfl_down_sync(full, acc, sh);
    if ((tid & 31) == 0) swarp[tid >> 5] = acc;
    __syncthreads();
    if (tid < 32) {
        double v = (tid < (TPB / 32)) ? swarp[tid] : 0.0;
        #pragma unroll
        for (int sh = 16; sh > 0; sh >>= 1) v += __shfl_down_sync(full, v, sh);
        if (tid == 0) g_partials[blockIdx.x] = v;
    }

    // ---- last-arriving block folds partials (deterministic order)
    if (tid == 0) {
        __threadfence();
        unsigned old = atomicInc(&g_counter, gridDim.x - 1);
        is_last = (old == gridDim.x - 1);
    }
    __syncthreads();
    if (is_last) {
        __threadfence();
        double v = 0.0;
        for (int i = tid; i < (int)gridDim.x; i += TPB) v += g_partials[i];
        #pragma unroll
        for (int sh = 16; sh > 0; sh >>= 1) v += __shfl_down_sync(full, v, sh);
        if ((tid & 31) == 0) swarp[tid >> 5] = v;
        __syncthreads();
        if (tid < 32) {
            double w = (tid < (TPB / 32)) ? swarp[tid] : 0.0;
            #pragma unroll
            for (int sh = 16; sh > 0; sh >>= 1) w += __shfl_down_sync(full, w, sh);
            if (tid == 0) out[0] = (float)w;
        }
    }
}

extern "C" void kernel_launch(void* const* d_in, const int* in_sizes, int n_in,
                              void* d_out, int out_size) {
    const float* pre = (const float*)d_in[0];
    const float* gt  = (const float*)d_in[1];
    float* out = (float*)d_out;

    const int nelem  = in_sizes[0];
    const int ncells = nelem / 30;
    const int ntiles = ncells / TILE_CELLS;            // full tiles (12544)

    int grid = ntiles < 148 ? (ntiles > 0 ? ntiles : 1) : 148;
    if (grid > MAX_BLOCKS) grid = MAX_BLOCKS;
    const int tiles_per_blk = (ntiles + grid - 1) / grid;

    cudaFuncSetAttribute(yolo_loss_tma,
                         cudaFuncAttributeMaxDynamicSharedMemorySize, SMEM_DYN);
    yolo_loss_tma<<<grid, TPB, SMEM_DYN>>>(pre, gt, out, ncells, ntiles,
                                           tiles_per_blk);
}